// round 4
// baseline (speedup 1.0000x reference)
#include <cuda_runtime.h>

// LearnableWaveletTransform: depthwise 1D cross-correlation, 2 shared 96-tap
// filters over x[64,128,4096] fp32, pad=48 -> out (l,h) each [64,128,4097].
//
// R3b (re-run of R3; previous round was an infra container failure):
// FFMA2 (fma.rn.f32x2) packing the two FILTERS into the fp32 lanes.
// RPT=16 outputs/thread -> fma fraction ~84% of issued instructions.
// One block per row (TILE=4096); t=4096 tail handled by one thread.
// Inner k-unroll of 16 == window depth so the register window rotates by
// pure renaming (no MOVs at the back edge).

#define KW      96
#define PADW    48
#define TLEN    4096
#define TOUT    4097
#define NROWS   8192            // 64 * 128
#define NTHREADS 256
#define RPT     16
#define TILE    (NTHREADS * RPT)        // 4096
#define WINLEN  (TILE + KW)             // 4192
#define HALFOFF ((long long)NROWS * (long long)TOUT)  // 33,562,624

__device__ __forceinline__ unsigned long long ffma2(unsigned long long a,
                                                    unsigned long long b,
                                                    unsigned long long c) {
    unsigned long long d;
    asm("fma.rn.f32x2 %0, %1, %2, %3;" : "=l"(d) : "l"(a), "l"(b), "l"(c));
    return d;
}
__device__ __forceinline__ unsigned long long pack2(float lo, float hi) {
    unsigned long long r;
    asm("mov.b64 %0, {%1, %2};" : "=l"(r) : "f"(lo), "f"(hi));
    return r;
}
__device__ __forceinline__ void unpack2(unsigned long long v, float& lo, float& hi) {
    asm("mov.b64 {%0, %1}, %2;" : "=f"(lo), "=f"(hi) : "l"(v));
}

__global__ void __launch_bounds__(NTHREADS)
wavelet_f32x2_r3(const float* __restrict__ x,
                 const float* __restrict__ hw,
                 const float* __restrict__ lw,
                 float* __restrict__ out)
{
    __shared__ float sx[WINLEN];
    __shared__ unsigned long long wp[KW];

    const int row = blockIdx.x;
    const int tid = threadIdx.x;

    const long long xbase = (long long)row * TLEN;

    // Cooperative window load (zero-padded at row boundaries).
    // sx[i] = x[row, i - PADW] (or 0 outside [0, TLEN))
    for (int i = tid; i < WINLEN; i += NTHREADS) {
        int g = i - PADW;
        sx[i] = (g >= 0 && g < TLEN) ? x[xbase + g] : 0.0f;
    }
    // Pack filters: lane.lo = l_w, lane.hi = h_w
    if (tid < KW) wp[tid] = pack2(lw[tid], hw[tid]);
    __syncthreads();

    const int s0 = tid * RPT;       // window start for this thread's outputs

    // Sliding window of duplicated-pair x values (16 deep)
    unsigned long long xd[RPT];
    #pragma unroll
    for (int j = 0; j < RPT; ++j) {
        float v = sx[s0 + j];
        xd[j] = pack2(v, v);
    }

    unsigned long long acc[RPT];
    #pragma unroll
    for (int j = 0; j < RPT; ++j) acc[j] = 0ULL;   // (+0.0f, +0.0f)

    // 96 taps = 6 outer x 16 inner; inner unroll equals window depth so the
    // rotation is consistent register renaming at the loop back edge.
    #pragma unroll 1
    for (int kk = 0; kk < KW; kk += RPT) {
        #pragma unroll
        for (int ki = 0; ki < RPT; ++ki) {
            const int k = kk + ki;
            unsigned long long w = wp[k];            // LDS64 broadcast
            #pragma unroll
            for (int j = 0; j < RPT; ++j)
                acc[j] = ffma2(xd[j], w, acc[j]);
            // shift window left, bring in next x (max idx s0+16+95 <= 4191)
            #pragma unroll
            for (int j = 0; j < RPT - 1; ++j) xd[j] = xd[j + 1];
            float v = sx[s0 + RPT + k];
            xd[RPT - 1] = pack2(v, v);
        }
    }

    const long long obase = (long long)row * TOUT;
    const int t0 = s0;              // == global t since one block per row
    #pragma unroll
    for (int j = 0; j < RPT; ++j) {
        float lo, hi;
        unpack2(acc[j], lo, hi);
        out[obase + t0 + j]           = lo;   // l_outs
        out[HALFOFF + obase + t0 + j] = hi;   // h_outs
    }

    // Tail output t = 4096 (window sx[4096..4191], zero-padded past row end)
    if (tid == NTHREADS - 1) {
        unsigned long long e = 0ULL;
        #pragma unroll 16
        for (int k = 0; k < KW; ++k) {
            float v = sx[TILE + k];
            e = ffma2(pack2(v, v), wp[k], e);
        }
        float lo, hi;
        unpack2(e, lo, hi);
        out[obase + TLEN]           = lo;
        out[HALFOFF + obase + TLEN] = hi;
    }
}

extern "C" void kernel_launch(void* const* d_in, const int* in_sizes, int n_in,
                              void* d_out, int out_size) {
    // metadata order: x, h_w, l_w ; output: (l_outs, h_outs) concatenated
    const float* x  = (const float*)d_in[0];
    const float* hw = (const float*)d_in[1];
    const float* lw = (const float*)d_in[2];
    float* out = (float*)d_out;

    dim3 grid(NROWS);
    dim3 block(NTHREADS);
    wavelet_f32x2_r3<<<grid, block>>>(x, hw, lw, out);
}

// round 6
// speedup vs baseline: 2.4603x; 2.4603x over previous
#include <cuda_runtime.h>

// LearnableWaveletTransform: depthwise 1D cross-correlation, 2 shared 96-tap
// filters over x[64,128,4096] fp32, pad=48 -> out (l,h) each [64,128,4097].
//
// R5: FFMA2 (fma.rn.f32x2) with both filters packed in the fp32 lanes, PLUS:
//  - SKEWED smem (phys = l + (l>>4)): lane-stride-16 window loads become
//    bank 17*lane mod 32 -> exactly conflict-free (was 16-way conflict).
//  - __launch_bounds__(256,3): cap regs at 84 -> 3 blocks/SM (was 2).
//  - Output staging through smem -> coalesced STG (was 8x sector-amplified).

#define KW      96
#define PADW    48
#define TLEN    4096
#define TOUT    4097
#define NROWS   8192            // 64 * 128
#define NTHREADS 256
#define RPT     16
#define TILE    (NTHREADS * RPT)        // 4096
#define WINLEN  (TILE + KW)             // 4192
#define SKEWLEN (WINLEN + (WINLEN >> 4))  // 4454
#define HALFOFF ((long long)NROWS * (long long)TOUT)  // 33,562,624

__device__ __forceinline__ int skew(int l) { return l + (l >> 4); }

__device__ __forceinline__ unsigned long long ffma2(unsigned long long a,
                                                    unsigned long long b,
                                                    unsigned long long c) {
    unsigned long long d;
    asm("fma.rn.f32x2 %0, %1, %2, %3;" : "=l"(d) : "l"(a), "l"(b), "l"(c));
    return d;
}
__device__ __forceinline__ unsigned long long pack2(float lo, float hi) {
    unsigned long long r;
    asm("mov.b64 %0, {%1, %2};" : "=l"(r) : "f"(lo), "f"(hi));
    return r;
}
__device__ __forceinline__ void unpack2(unsigned long long v, float& lo, float& hi) {
    asm("mov.b64 {%0, %1}, %2;" : "=f"(lo), "=f"(hi) : "l"(v));
}

__global__ void __launch_bounds__(NTHREADS, 3)
wavelet_f32x2_r5(const float* __restrict__ x,
                 const float* __restrict__ hw,
                 const float* __restrict__ lw,
                 float* __restrict__ out)
{
    __shared__ float sxs[SKEWLEN];
    __shared__ unsigned long long wp[KW];

    const int row = blockIdx.x;
    const int tid = threadIdx.x;
    const long long xbase = (long long)row * TLEN;

    // Skewed cooperative window fill: sxs[skew(i)] = x[row, i - PADW] (0-pad)
    for (int i = tid; i < WINLEN; i += NTHREADS) {
        int g = i - PADW;
        sxs[skew(i)] = (g >= 0 && g < TLEN) ? x[xbase + g] : 0.0f;
    }
    if (tid < KW) wp[tid] = pack2(lw[tid], hw[tid]);   // lane.lo=l, lane.hi=h
    __syncthreads();

    const int s0 = tid * RPT;

    // Sliding register window of duplicated-pair x values (16 deep)
    unsigned long long xd[RPT];
    #pragma unroll
    for (int j = 0; j < RPT; ++j) {
        float v = sxs[skew(s0 + j)];
        xd[j] = pack2(v, v);
    }

    unsigned long long acc[RPT];
    #pragma unroll
    for (int j = 0; j < RPT; ++j) acc[j] = 0ULL;

    // 96 taps = 6 outer x 16 inner; inner unroll == window depth so the
    // rotation is pure register renaming at the back edge.
    #pragma unroll 1
    for (int kk = 0; kk < KW; kk += RPT) {
        #pragma unroll
        for (int ki = 0; ki < RPT; ++ki) {
            const int k = kk + ki;
            unsigned long long w = wp[k];            // broadcast LDS64
            #pragma unroll
            for (int j = 0; j < RPT; ++j)
                acc[j] = ffma2(xd[j], w, acc[j]);
            #pragma unroll
            for (int j = 0; j < RPT - 1; ++j) xd[j] = xd[j + 1];
            float v = sxs[skew(s0 + RPT + k)];       // bank 17*lane: no conflict
            xd[RPT - 1] = pack2(v, v);
        }
    }

    // Unpack accumulators
    float lacc[RPT], hacc[RPT];
    #pragma unroll
    for (int j = 0; j < RPT; ++j) unpack2(acc[j], lacc[j], hacc[j]);

    // Tail output t = 4096 (one thread; uses sxs before it's overwritten)
    float tl = 0.0f, th = 0.0f;
    if (tid == NTHREADS - 1) {
        unsigned long long e = 0ULL;
        #pragma unroll 16
        for (int k = 0; k < KW; ++k) {
            float v = sxs[skew(TILE + k)];
            e = ffma2(pack2(v, v), wp[k], e);
        }
        unpack2(e, tl, th);
    }

    const long long obase = (long long)row * TOUT;

    // ── Stage l through smem -> coalesced STG ──
    __syncthreads();                       // everyone done reading sxs
    #pragma unroll
    for (int j = 0; j < RPT; ++j) sxs[skew(s0 + j)] = lacc[j];  // conflict-free
    __syncthreads();
    #pragma unroll
    for (int j = 0; j < RPT; ++j) {
        int t = tid + j * NTHREADS;        // lane-consecutive -> coalesced
        out[obase + t] = sxs[skew(t)];
    }

    // ── Stage h ──
    __syncthreads();
    #pragma unroll
    for (int j = 0; j < RPT; ++j) sxs[skew(s0 + j)] = hacc[j];
    __syncthreads();
    #pragma unroll
    for (int j = 0; j < RPT; ++j) {
        int t = tid + j * NTHREADS;
        out[HALFOFF + obase + t] = sxs[skew(t)];
    }

    if (tid == NTHREADS - 1) {
        out[obase + TLEN]           = tl;
        out[HALFOFF + obase + TLEN] = th;
    }
}

extern "C" void kernel_launch(void* const* d_in, const int* in_sizes, int n_in,
                              void* d_out, int out_size) {
    // metadata order: x, h_w, l_w ; output: (l_outs, h_outs) concatenated
    const float* x  = (const float*)d_in[0];
    const float* hw = (const float*)d_in[1];
    const float* lw = (const float*)d_in[2];
    float* out = (float*)d_out;

    dim3 grid(NROWS);
    dim3 block(NTHREADS);
    wavelet_f32x2_r5<<<grid, block>>>(x, hw, lw, out);
}